// round 3
// baseline (speedup 1.0000x reference)
#include <cuda_runtime.h>
#include <stdint.h>

// TestSpatialTransform == two center crops of (4,2,192,192,192) -> (4,2,160,160,160).
// Pure HBM copy at ~minimum traffic. Each thread covers ONE crop position
// (d,h,w4) across ALL 8 bc-slices of BOTH tensors: 16 independent LDG.128
// front-batched (deep L1tex queue -> high DRAM busy), one index computation.

#define PATCH 160
#define SRC   192
#define OFF   16
#define BC    8                        // B*C = 4*2
#define W4    (PATCH / 4)              // 40 float4 per row
#define SRC3  (SRC * SRC * SRC)        // 7,077,888 floats per bc-slice
#define N_POS (PATCH * PATCH * W4)     // 1,024,000 positions (d,h,w4)
#define N_F4_PER_TENSOR (BC * N_POS)   // 8,192,000

__global__ void __launch_bounds__(256)
crop_copy16_kernel(const float* __restrict__ data,
                   const float* __restrict__ seg,
                   float4* __restrict__ out)
{
    int idx = blockIdx.x * blockDim.x + threadIdx.x;   // 0 .. N_POS-1 (exact grid)

    int w4 = idx % W4;
    int t  = idx / W4;
    int h  = t % PATCH;
    int d  = t / PATCH;

    // source flat float index within one (192,192,192) slice
    int sidx = ((d + OFF) * SRC + (h + OFF)) * SRC + OFF + (w4 << 2);

    float4 a[BC], b[BC];
#pragma unroll
    for (int bc = 0; bc < BC; bc++) {
        a[bc] = __ldcs(reinterpret_cast<const float4*>(data + sidx + bc * SRC3));
        b[bc] = __ldcs(reinterpret_cast<const float4*>(seg  + sidx + bc * SRC3));
    }
#pragma unroll
    for (int bc = 0; bc < BC; bc++) {
        __stcs(out + idx + bc * N_POS, a[bc]);
        __stcs(out + idx + bc * N_POS + N_F4_PER_TENSOR, b[bc]);
    }
}

extern "C" void kernel_launch(void* const* d_in, const int* in_sizes, int n_in,
                              void* d_out, int out_size)
{
    const float* data = (const float*)d_in[0];
    const float* seg  = (const float*)d_in[1];
    float4* out = (float4*)d_out;

    const int threads = 256;
    const int blocks  = N_POS / threads;   // 4000 exactly, no tail
    crop_copy16_kernel<<<blocks, threads>>>(data, seg, out);
}